// round 3
// baseline (speedup 1.0000x reference)
#include <cuda_runtime.h>
#include <cuda_bf16.h>
#include <mma.h>

using namespace nvcuda;

#define HEAD_DIM     128
#define NUM_SEQS     8
#define SEQ_LEN      512
#define Q_HEADS      16
#define TOTAL_TOKENS 4096
#define ROW_STRIDE   (Q_HEADS * HEAD_DIM)   // 2048 floats per token row

#define BM 64          // q rows per CTA
#define BN 64          // kv rows per tile
#define LDT 132        // padded leading dim for Q/K/V tiles (multiple of 4)
#define LDS 68         // padded leading dim for S tile (multiple of 4)

#define NTHREADS 256
#define SCALE 0.08838834764831845f  // 1/sqrt(128)

#define SMEM_FLOATS (3 * BM * LDT + BM * LDS)
#define SMEM_BYTES  (SMEM_FLOATS * (int)sizeof(float))

__device__ __forceinline__ void load_tile_scaled(float* dst, const float* src,
                                                 int row0, int head, float scale,
                                                 int tid) {
    // 64 rows x 128 cols, float4 per thread-iter
    #pragma unroll
    for (int i = tid; i < BM * (HEAD_DIM / 4); i += NTHREADS) {
        int r  = i >> 5;        // /32
        int c4 = i & 31;
        int gr = row0 + r;
        if (gr >= TOTAL_TOKENS) gr = TOTAL_TOKENS - 1;
        float4 vv = *(const float4*)&src[(size_t)gr * ROW_STRIDE + head * HEAD_DIM + c4 * 4];
        vv.x *= scale; vv.y *= scale; vv.z *= scale; vv.w *= scale;
        float* d = dst + r * LDT + c4 * 4;
        d[0] = vv.x; d[1] = vv.y; d[2] = vv.z; d[3] = vv.w;
    }
}

__device__ __forceinline__ void cvt_tf32_a(
    wmma::fragment<wmma::matrix_a, 16, 16, 8, wmma::precision::tf32, wmma::row_major>& f) {
    #pragma unroll
    for (int i = 0; i < f.num_elements; i++) f.x[i] = wmma::__float_to_tf32(f.x[i]);
}
template <typename FragB>
__device__ __forceinline__ void cvt_tf32_b(FragB& f) {
    #pragma unroll
    for (int i = 0; i < f.num_elements; i++) f.x[i] = wmma::__float_to_tf32(f.x[i]);
}

// Compute S = Qs @ Ks^T for this warp's (stripe, halfw) quarter, write to Ss.
__device__ __forceinline__ void compute_S(const float* Qs, const float* Ks, float* Ss,
                                          int stripe, int halfw) {
    wmma::fragment<wmma::accumulator, 16, 16, 8, float> sacc[2];
    wmma::fill_fragment(sacc[0], 0.0f);
    wmma::fill_fragment(sacc[1], 0.0f);
    #pragma unroll
    for (int ks = 0; ks < HEAD_DIM / 8; ks++) {
        wmma::fragment<wmma::matrix_a, 16, 16, 8, wmma::precision::tf32, wmma::row_major> a;
        wmma::load_matrix_sync(a, Qs + (stripe * 16) * LDT + ks * 8, LDT);
        cvt_tf32_a(a);
        #pragma unroll
        for (int nf = 0; nf < 2; nf++) {
            wmma::fragment<wmma::matrix_b, 16, 16, 8, wmma::precision::tf32, wmma::col_major> b;
            wmma::load_matrix_sync(b, Ks + (halfw * 32 + nf * 16) * LDT + ks * 8, LDT);
            cvt_tf32_b(b);
            wmma::mma_sync(sacc[nf], a, b, sacc[nf]);
        }
    }
    #pragma unroll
    for (int nf = 0; nf < 2; nf++) {
        wmma::store_matrix_sync(Ss + (stripe * 16) * LDS + halfw * 32 + nf * 16,
                                sacc[nf], LDS, wmma::mem_row_major);
    }
}

__global__ void __launch_bounds__(NTHREADS, 1)
varlen_attn_kernel(const float* __restrict__ Q, const float* __restrict__ K,
                   const float* __restrict__ V, const int* __restrict__ ntok32,
                   float* __restrict__ Out) {
    extern __shared__ float sm[];
    float* Qs = sm;                       // BM x LDT
    float* Ks = Qs + BM * LDT;            // BN x LDT
    float* Vs = Ks + BM * LDT;            // BN x LDT
    float* Ss = Vs + BM * LDT;            // BM x LDS
    __shared__ float m_sh[BM];
    __shared__ float l_sh[BM];

    const int qb = blockIdx.x;   // q tile within seq
    const int h  = blockIdx.y;   // head
    const int s  = blockIdx.z;   // seq

    // num_tokens dtype sniff: int64 little-endian positive lengths have the
    // high word (elem 1) == 0; int32 has the second length (>0) there.
    const int tstride = (ntok32[1] == 0) ? 2 : 1;

    int seq_start = 0;
    for (int i = 0; i < s; i++) seq_start += ntok32[i * tstride];
    const int seq_len = ntok32[s * tstride];
    if (qb * BM >= seq_len) return;

    const int q0 = seq_start + qb * BM;

    const int tid    = threadIdx.x;
    const int warp   = tid >> 5;
    const int stripe = warp >> 1;   // 0..3 : which 16-row stripe
    const int halfw  = warp & 1;    // 0/1  : which half of the n range

    // ---- load Q tile (pre-scaled) ----
    load_tile_scaled(Qs, Q, q0, h, SCALE, tid);
    if (tid < BM) { m_sh[tid] = -1e30f; l_sh[tid] = 0.0f; }
    __syncthreads();

    const int nkv = (seq_len + BN - 1) / BN;

    // =============== PASS 1: softmax stats (m, l) ===============
    for (int kb = 0; kb < nkv; kb++) {
        load_tile_scaled(Ks, K, seq_start + kb * BN, h, 1.0f, tid);
        __syncthreads();

        compute_S(Qs, Ks, Ss, stripe, halfw);
        __syncthreads();

        const int klen = min(BN, seq_len - kb * BN);
        {
            const int r   = tid >> 2;
            const int qtr = tid & 3;
            const float* srow = Ss + r * LDS + qtr * 16;
            float mx = -1e30f;
            #pragma unroll
            for (int j = 0; j < 16; j++) {
                if (qtr * 16 + j < klen) mx = fmaxf(mx, srow[j]);
            }
            #pragma unroll
            for (int o = 1; o < 4; o <<= 1)
                mx = fmaxf(mx, __shfl_xor_sync(0xffffffffu, mx, o));
            const float m_old = m_sh[r];
            const float m_new = fmaxf(m_old, mx);
            float sum = 0.0f;
            #pragma unroll
            for (int j = 0; j < 16; j++) {
                if (qtr * 16 + j < klen) sum += __expf(srow[j] - m_new);
            }
            #pragma unroll
            for (int o = 1; o < 4; o <<= 1)
                sum += __shfl_xor_sync(0xffffffffu, sum, o);
            if (qtr == 0) {
                l_sh[r] = l_sh[r] * __expf(m_old - m_new) + sum;
                m_sh[r] = m_new;
            }
        }
        __syncthreads();
    }

    // invert l
    if (tid < BM) l_sh[tid] = 1.0f / l_sh[tid];
    __syncthreads();

    // =============== PASS 2: O = softmax(S) @ V ===============
    wmma::fragment<wmma::accumulator, 16, 16, 8, float> oacc[4];
    #pragma unroll
    for (int nf = 0; nf < 4; nf++) wmma::fill_fragment(oacc[nf], 0.0f);

    for (int kb = 0; kb < nkv; kb++) {
        load_tile_scaled(Ks, K, seq_start + kb * BN, h, 1.0f, tid);
        load_tile_scaled(Vs, V, seq_start + kb * BN, h, 1.0f, tid);
        __syncthreads();

        compute_S(Qs, Ks, Ss, stripe, halfw);
        __syncthreads();

        const int klen = min(BN, seq_len - kb * BN);
        #pragma unroll 4
        for (int i = tid; i < BM * BN; i += NTHREADS) {
            const int r = i >> 6;
            const int j = i & 63;
            float p = 0.0f;
            if (j < klen) p = __expf(Ss[r * LDS + j] - m_sh[r]) * l_sh[r];
            Ss[r * LDS + j] = p;
        }
        __syncthreads();

        // O += P @ V : A = P (row-major, ld=LDS), B = V (row-major, ld=LDT)
        #pragma unroll
        for (int ks = 0; ks < BN / 8; ks++) {
            wmma::fragment<wmma::matrix_a, 16, 16, 8, wmma::precision::tf32, wmma::row_major> a;
            wmma::load_matrix_sync(a, Ss + (stripe * 16) * LDS + ks * 8, LDS);
            cvt_tf32_a(a);
            #pragma unroll
            for (int nf = 0; nf < 4; nf++) {
                wmma::fragment<wmma::matrix_b, 16, 16, 8, wmma::precision::tf32, wmma::row_major> b;
                wmma::load_matrix_sync(b, Vs + (ks * 8) * LDT + halfw * 64 + nf * 16, LDT);
                cvt_tf32_b(b);
                wmma::mma_sync(oacc[nf], a, b, oacc[nf]);
            }
        }
        __syncthreads();
    }

    // ---- store O: out[h][t][d], t stride = HEAD_DIM ----
    float* op = Out + ((size_t)h * TOTAL_TOKENS + (size_t)(q0 + stripe * 16)) * HEAD_DIM
                    + halfw * 64;
    #pragma unroll
    for (int nf = 0; nf < 4; nf++) {
        wmma::store_matrix_sync(op + nf * 16, oacc[nf], HEAD_DIM, wmma::mem_row_major);
    }
}

extern "C" void kernel_launch(void* const* d_in, const int* in_sizes, int n_in,
                              void* d_out, int out_size) {
    const float* Q = (const float*)d_in[0];
    const float* K = (const float*)d_in[1];
    const float* V = (const float*)d_in[2];
    const int* ntok = (const int*)d_in[3];
    float* Out = (float*)d_out;

    cudaFuncSetAttribute(varlen_attn_kernel,
                         cudaFuncAttributeMaxDynamicSharedMemorySize, SMEM_BYTES);

    dim3 grid(SEQ_LEN / BM, Q_HEADS, NUM_SEQS);
    varlen_attn_kernel<<<grid, NTHREADS, SMEM_BYTES>>>(Q, K, V, ntok, Out);
}